// round 9
// baseline (speedup 1.0000x reference)
#include <cuda_runtime.h>
#include <cuda_bf16.h>
#include <stdint.h>

// Problem constants
#define BSZ 8
#define SEQ 4096
#define HID 1024
#define NEXP 8
#define CAP 512
#define NTOK (BSZ * SEQ)           // 32768
#define NPAIR (BSZ * NEXP)         // 64
#define IDX_OFF 0
#define SCORE_OFF (NPAIR * CAP)    // 32768
#define MASK_OFF (2 * NPAIR * CAP) // 65536

// Scratch (device globals; no allocation allowed)
__device__ float g_aff[NPAIR * SEQ];   // affinity [b*8+e][s]
__device__ int   g_idx[NPAIR * CAP];

// ---------------------------------------------------------------------------
// Kernel 1: gating. GEMM emulates a gemv-style reduction kernel with 128-bit
// vectorized strided partition:
//   lane L accumulates k = 4L + j + 128 i  (j = 0..3 inner, i = 0..7 outer,
//   single fp32 accumulator, FMA), then warp tree combine (xor-butterfly ==
//   shfl.down tree bitwise for every lane's final value pairing).
// Softmax: exact max, fsub.rn, libdevice expf, strictly sequential sum
// e = 0..7, IEEE division per element.
// 8 warps/block, 4 tokens/warp.
// ---------------------------------------------------------------------------
__global__ __launch_bounds__(256) void gate_kernel(const float* __restrict__ hid,
                                                   const float* __restrict__ w)
{
    __shared__ float ws[NEXP * HID];   // ws[e*1024 + k], e-major (conflict-free)
    int tid = threadIdx.x;
    for (int i = tid; i < HID * NEXP; i += 256) {
        int k = i >> 3, e = i & 7;
        ws[e * HID + k] = w[i];
    }
    __syncthreads();

    int warp = tid >> 5, lane = tid & 31;
    int tok0 = (blockIdx.x * 8 + warp) * 4;   // 4 tokens per warp

    float acc[4][8];
#pragma unroll
    for (int t = 0; t < 4; t++)
#pragma unroll
        for (int e = 0; e < 8; e++) acc[t][e] = 0.0f;

    const float* h0 = hid + (size_t)tok0 * HID;

    // vectorized strided accumulation: k = lane*4 + j + 128*i, j inner
#pragma unroll
    for (int i = 0; i < 8; i++) {
        int kbase = i * 128 + lane * 4;
        float wreg[8][4];
#pragma unroll
        for (int e = 0; e < 8; e++)
#pragma unroll
            for (int j = 0; j < 4; j++)
                wreg[e][j] = ws[e * HID + kbase + j];
#pragma unroll
        for (int t = 0; t < 4; t++) {
            float4 h4 = *(const float4*)(h0 + (size_t)t * HID + kbase);
            float hj[4] = {h4.x, h4.y, h4.z, h4.w};
#pragma unroll
            for (int e = 0; e < 8; e++) {
#pragma unroll
                for (int j = 0; j < 4; j++)
                    acc[t][e] = __fmaf_rn(hj[j], wreg[e][j], acc[t][e]);
            }
        }
    }

    // warp tree combine (pairing == shfl.down reduction bitwise)
#pragma unroll
    for (int off = 16; off > 0; off >>= 1) {
#pragma unroll
        for (int t = 0; t < 4; t++)
#pragma unroll
            for (int e = 0; e < 8; e++)
                acc[t][e] = __fadd_rn(acc[t][e],
                                      __shfl_xor_sync(0xFFFFFFFFu, acc[t][e], off));
    }

    // lanes 0..3 each own one token: softmax over 8 experts
    if (lane < 4) {
        int tok = tok0 + lane;
        int b = tok >> 12;
        int s = tok & (SEQ - 1);

        float m = acc[lane][0];
#pragma unroll
        for (int e = 1; e < 8; e++) m = fmaxf(m, acc[lane][e]);  // exact op

        float ex[8];
        float sum = 0.0f;
#pragma unroll
        for (int e = 0; e < 8; e++) {
            float d = __fsub_rn(acc[lane][e], m);
            ex[e] = expf(d);                    // libdevice __nv_expf
            sum = __fadd_rn(sum, ex[e]);        // strictly sequential e = 0..7
        }
#pragma unroll
        for (int e = 0; e < 8; e++)
            g_aff[((size_t)(b * NEXP + e)) * SEQ + s] = __fdiv_rn(ex[e], sum);
    }
}

// ---------------------------------------------------------------------------
// Kernel 2: per-(b,e) bitonic sort (descending) of 4096 packed keys.
// Key = (float_bits << 32) | ~index : descending by value, ascending index
// on exact fp32 ties (matches jax.lax.top_k stability).
// ---------------------------------------------------------------------------
__global__ __launch_bounds__(512) void topk_kernel(float* __restrict__ out)
{
    __shared__ unsigned long long keys[SEQ];
    int pair = blockIdx.x;
    const float* a = g_aff + (size_t)pair * SEQ;

    for (int si = threadIdx.x; si < SEQ; si += 512) {
        unsigned int fb = __float_as_uint(a[si]);   // softmax output > 0
        keys[si] = ((unsigned long long)fb << 32) | (unsigned int)(~si);
    }
    __syncthreads();

    for (int k = 2; k <= SEQ; k <<= 1) {
        for (int j = k >> 1; j > 0; j >>= 1) {
#pragma unroll 4
            for (int i = threadIdx.x; i < SEQ; i += 512) {
                int ixj = i ^ j;
                if (ixj > i) {
                    unsigned long long x = keys[i], y = keys[ixj];
                    bool desc = ((i & k) == 0);
                    if (desc ? (x < y) : (x > y)) { keys[i] = y; keys[ixj] = x; }
                }
            }
            __syncthreads();
        }
    }

    int cslot = threadIdx.x;            // 512 threads == CAP
    unsigned long long key = keys[cslot];
    int   si = (int)(~(unsigned int)key);
    float v  = __uint_as_float((unsigned int)(key >> 32));
    out[IDX_OFF + pair * CAP + cslot]   = (float)si;  // topk_indices (as float)
    out[SCORE_OFF + pair * CAP + cslot] = v;          // topk_scores (SCALE=1.0)
    g_idx[pair * CAP + cslot] = si;
}

// ---------------------------------------------------------------------------
// Kernel 3: dispatch mask. One block per (pair, slot) row of 4096 floats.
// Single pass: vectorized zero fill + drop the single 1.0.
// ---------------------------------------------------------------------------
__global__ __launch_bounds__(256) void mask_kernel(float* __restrict__ out)
{
    int row = blockIdx.x;                       // 0 .. 32767
    float* rowp = out + MASK_OFF + (size_t)row * SEQ;
    float4* row4 = (float4*)rowp;
    float4 z = make_float4(0.f, 0.f, 0.f, 0.f);
#pragma unroll
    for (int q = threadIdx.x; q < SEQ / 4; q += 256)
        row4[q] = z;
    __syncthreads();
    if (threadIdx.x == 0)
        rowp[g_idx[row]] = 1.0f;
}

extern "C" void kernel_launch(void* const* d_in, const int* in_sizes, int n_in,
                              void* d_out, int out_size)
{
    const float* hid = (const float*)d_in[0];   // [8, 4096, 1024] fp32
    const float* w   = (const float*)d_in[1];   // [1024, 8] fp32
    float* out = (float*)d_out;

    gate_kernel<<<NTOK / 32, 256>>>(hid, w);    // 1024 blocks
    topk_kernel<<<NPAIR, 512>>>(out);           // 64 blocks
    mask_kernel<<<NPAIR * CAP, 256>>>(out);     // 32768 blocks
}

// round 10
// speedup vs baseline: 1.0872x; 1.0872x over previous
#include <cuda_runtime.h>
#include <cuda_bf16.h>
#include <stdint.h>

// Problem constants
#define BSZ 8
#define SEQ 4096
#define HID 1024
#define NEXP 8
#define CAP 512
#define NTOK (BSZ * SEQ)           // 32768
#define NPAIR (BSZ * NEXP)         // 64
#define IDX_OFF 0
#define SCORE_OFF (NPAIR * CAP)    // 32768
#define MASK_OFF (2 * NPAIR * CAP) // 65536
#define MASK_FLOATS (NPAIR * CAP * SEQ)   // 134217728

#define GATE_BLOCKS 1024           // 8 warps x 4 tokens = 32 tokens/block
#define ZF_BLOCKS   4096           // zero-fill blocks, 32768 floats each
#define ZF_PER_BLK  (MASK_FLOATS / ZF_BLOCKS)   // 32768 floats = 8192 float4

// Scratch (device global; no allocation allowed)
__device__ float g_aff[NPAIR * SEQ];   // affinity [b*8+e][s]

// ---------------------------------------------------------------------------
// Kernel A (fused): gating + dispatch-mask zero-fill.
//  - blocks [0, GATE_BLOCKS):   gate, arithmetic FROZEN bit-exact from R9:
//      lane L accumulates k = 4L + j + 128 i (j inner, i outer, single fp32
//      FMA accumulator), xor-butterfly tree combine, exact max, fsub.rn,
//      libdevice expf, sequential e-sum, __fdiv_rn.
//  - blocks [GATE_BLOCKS, +ZF_BLOCKS): stream float4 zeros over the mask
//      region, soaking up the HBM bandwidth the gate leaves idle.
// ---------------------------------------------------------------------------
__global__ __launch_bounds__(256) void fused_gate_zf_kernel(
    const float* __restrict__ hid, const float* __restrict__ w,
    float* __restrict__ out)
{
    __shared__ float ws[NEXP * HID];   // ws[e*1024 + k], e-major
    int tid = threadIdx.x;

    if (blockIdx.x >= GATE_BLOCKS) {
        // ---- mask zero-fill path ----
        size_t base = (size_t)MASK_OFF +
                      (size_t)(blockIdx.x - GATE_BLOCKS) * ZF_PER_BLK;
        float4* dst = (float4*)(out + base);
        float4 z = make_float4(0.f, 0.f, 0.f, 0.f);
#pragma unroll
        for (int q = tid; q < ZF_PER_BLK / 4; q += 256)
            dst[q] = z;
        return;
    }

    // ---- gate path (bit-exact, frozen) ----
    for (int i = tid; i < HID * NEXP; i += 256) {
        int k = i >> 3, e = i & 7;
        ws[e * HID + k] = w[i];
    }
    __syncthreads();

    int warp = tid >> 5, lane = tid & 31;
    int tok0 = (blockIdx.x * 8 + warp) * 4;   // 4 tokens per warp

    float acc[4][8];
#pragma unroll
    for (int t = 0; t < 4; t++)
#pragma unroll
        for (int e = 0; e < 8; e++) acc[t][e] = 0.0f;

    const float* h0 = hid + (size_t)tok0 * HID;

    // vectorized strided accumulation: k = lane*4 + j + 128*i, j inner
#pragma unroll
    for (int i = 0; i < 8; i++) {
        int kbase = i * 128 + lane * 4;
        float wreg[8][4];
#pragma unroll
        for (int e = 0; e < 8; e++)
#pragma unroll
            for (int j = 0; j < 4; j++)
                wreg[e][j] = ws[e * HID + kbase + j];
#pragma unroll
        for (int t = 0; t < 4; t++) {
            float4 h4 = *(const float4*)(h0 + (size_t)t * HID + kbase);
            float hj[4] = {h4.x, h4.y, h4.z, h4.w};
#pragma unroll
            for (int e = 0; e < 8; e++) {
#pragma unroll
                for (int j = 0; j < 4; j++)
                    acc[t][e] = __fmaf_rn(hj[j], wreg[e][j], acc[t][e]);
            }
        }
    }

    // warp tree combine (pairing == shfl.down reduction bitwise)
#pragma unroll
    for (int off = 16; off > 0; off >>= 1) {
#pragma unroll
        for (int t = 0; t < 4; t++)
#pragma unroll
            for (int e = 0; e < 8; e++)
                acc[t][e] = __fadd_rn(acc[t][e],
                                      __shfl_xor_sync(0xFFFFFFFFu, acc[t][e], off));
    }

    // lanes 0..3 each own one token: softmax over 8 experts
    if (lane < 4) {
        int tok = tok0 + lane;
        int b = tok >> 12;
        int s = tok & (SEQ - 1);

        float m = acc[lane][0];
#pragma unroll
        for (int e = 1; e < 8; e++) m = fmaxf(m, acc[lane][e]);  // exact op

        float ex[8];
        float sum = 0.0f;
#pragma unroll
        for (int e = 0; e < 8; e++) {
            float d = __fsub_rn(acc[lane][e], m);
            ex[e] = expf(d);                    // libdevice __nv_expf
            sum = __fadd_rn(sum, ex[e]);        // strictly sequential e = 0..7
        }
#pragma unroll
        for (int e = 0; e < 8; e++)
            g_aff[((size_t)(b * NEXP + e)) * SEQ + s] = __fdiv_rn(ex[e], sum);
    }
}

// ---------------------------------------------------------------------------
// Kernel B: per-(b,e) bitonic sort (descending) of 4096 packed keys,
// then write indices + scores + the one-hot 1.0s into the (pre-zeroed) mask.
// Key = (float_bits << 32) | ~index : descending by value, ascending index
// on exact fp32 ties (matches jax.lax.top_k stability). 1024 threads.
// ---------------------------------------------------------------------------
__global__ __launch_bounds__(1024) void topk_kernel(float* __restrict__ out)
{
    __shared__ unsigned long long keys[SEQ];
    int pair = blockIdx.x;
    const float* a = g_aff + (size_t)pair * SEQ;

    for (int si = threadIdx.x; si < SEQ; si += 1024) {
        unsigned int fb = __float_as_uint(a[si]);   // softmax output > 0
        keys[si] = ((unsigned long long)fb << 32) | (unsigned int)(~si);
    }
    __syncthreads();

    for (int k = 2; k <= SEQ; k <<= 1) {
        for (int j = k >> 1; j > 0; j >>= 1) {
#pragma unroll 2
            for (int i = threadIdx.x; i < SEQ; i += 1024) {
                int ixj = i ^ j;
                if (ixj > i) {
                    unsigned long long x = keys[i], y = keys[ixj];
                    bool desc = ((i & k) == 0);
                    if (desc ? (x < y) : (x > y)) { keys[i] = y; keys[ixj] = x; }
                }
            }
            __syncthreads();
        }
    }

    int cslot = threadIdx.x;
    if (cslot < CAP) {
        unsigned long long key = keys[cslot];
        int   si = (int)(~(unsigned int)key);
        float v  = __uint_as_float((unsigned int)(key >> 32));
        int row = pair * CAP + cslot;
        out[IDX_OFF + row]   = (float)si;   // topk_indices (as float)
        out[SCORE_OFF + row] = v;           // topk_scores (SCALE=1.0)
        out[MASK_OFF + (size_t)row * SEQ + si] = 1.0f;   // one-hot
    }
}

extern "C" void kernel_launch(void* const* d_in, const int* in_sizes, int n_in,
                              void* d_out, int out_size)
{
    const float* hid = (const float*)d_in[0];   // [8, 4096, 1024] fp32
    const float* w   = (const float*)d_in[1];   // [1024, 8] fp32
    float* out = (float*)d_out;

    fused_gate_zf_kernel<<<GATE_BLOCKS + ZF_BLOCKS, 256>>>(hid, w, out);
    topk_kernel<<<NPAIR, 1024>>>(out);
}